// round 9
// baseline (speedup 1.0000x reference)
#include <cuda_runtime.h>
#include <cuda_bf16.h>
#include <math.h>

#define D     512
#define KTOP  11          // 1 + K
#define KNEI  9           // reference uses idx[1:K] = 9 neighbors
#define NCLS  100
#define GRID1 1480        // ~169 rows/block
#define SKN   176         // smem key slots per block (>= ceil(250000/1480)=169)
#define NCAND (GRID1 * KTOP)                  // 16280
#define MBLK  ((NCAND + 255) / 256)           // 64 merge blocks
#define NC2   (MBLK * KTOP)                   // 704

// Scratch (allocation-free rule: __device__ globals)
__device__ unsigned long long g_cand[NCAND];
__device__ unsigned long long g_cand2[NC2];

// ---- monotonic float key: bigger key == bigger value; tie -> smaller index wins ----
__device__ __forceinline__ unsigned long long make_key(float v, unsigned int idx) {
    unsigned int b = __float_as_uint(v);
    b = (b & 0x80000000u) ? ~b : (b | 0x80000000u);
    return ((unsigned long long)b << 32) | (unsigned int)(~idx);
}
__device__ __forceinline__ float key_val(unsigned long long k) {
    unsigned int o = (unsigned int)(k >> 32);
    unsigned int b = (o & 0x80000000u) ? (o ^ 0x80000000u) : ~o;
    return __uint_as_float(b);
}
__device__ __forceinline__ unsigned int key_idx(unsigned long long k) {
    return ~(unsigned int)(k & 0xFFFFFFFFu);
}

__device__ __forceinline__ unsigned long long warp_max_u64(unsigned long long v) {
    #pragma unroll
    for (int o = 16; o; o >>= 1) {
        unsigned long long u = __shfl_xor_sync(0xFFFFFFFFu, v, o);
        if (u > v) v = u;
    }
    return v;
}

__device__ __forceinline__ unsigned long long block_max_u64(unsigned long long v,
                                                            unsigned long long* sh) {
    v = warp_max_u64(v);
    int warp = threadIdx.x >> 5, lane = threadIdx.x & 31;
    if (lane == 0) sh[warp] = v;
    __syncthreads();
    if (warp == 0) {
        int nw = (blockDim.x + 31) >> 5;
        v = (lane < nw) ? sh[lane] : 0ULL;
        #pragma unroll
        for (int o = 4; o; o >>= 1) {
            unsigned long long u = __shfl_xor_sync(0xFFFFFFFFu, v, o);
            if (u > v) v = u;
        }
        if (lane == 0) sh[0] = v;
    }
    __syncthreads();
    unsigned long long r = sh[0];
    __syncthreads();
    return r;
}

// ---------- Kernel 1: software-pipelined streaming dot+sumsq + per-block top-11 ----------
__global__ void __launch_bounds__(256) score_topk_kernel(
        const float* __restrict__ coll, const float* __restrict__ emb, int n) {
    __shared__ float4 sq[D / 4];
    __shared__ unsigned long long skeys[SKN];
    __shared__ unsigned long long sh[33];

    int t = threadIdx.x;
    if (t < D / 4) sq[t] = reinterpret_cast<const float4*>(emb)[t];
    if (t < SKN) skeys[t] = 0ULL;
    __syncthreads();

    int warp = t >> 5, lane = t & 31;
    int rbeg = (int)(((long long)n * blockIdx.x) / GRID1);
    int rend = (int)(((long long)n * (blockIdx.x + 1)) / GRID1);
    int cnt  = rend - rbeg;

    // prologue: load first row for this warp
    int local = warp;
    float4 a0, a1, a2, a3;
    if (local < cnt) {
        const float4* rp = reinterpret_cast<const float4*>(coll + (size_t)(rbeg + local) * D);
        a0 = __ldcs(rp + lane);
        a1 = __ldcs(rp + lane + 32);
        a2 = __ldcs(rp + lane + 64);
        a3 = __ldcs(rp + lane + 96);
    }
    while (local < cnt) {
        // issue next row's loads BEFORE reducing current row (overlap shfl chain with DRAM)
        int nlocal = local + 8;
        float4 b0, b1, b2, b3;
        if (nlocal < cnt) {
            const float4* rp = reinterpret_cast<const float4*>(coll + (size_t)(rbeg + nlocal) * D);
            b0 = __ldcs(rp + lane);
            b1 = __ldcs(rp + lane + 32);
            b2 = __ldcs(rp + lane + 64);
            b3 = __ldcs(rp + lane + 96);
        }
        float4 q0 = sq[lane], q1 = sq[lane + 32], q2 = sq[lane + 64], q3 = sq[lane + 96];
        float dot = a0.x*q0.x + a0.y*q0.y + a0.z*q0.z + a0.w*q0.w
                  + a1.x*q1.x + a1.y*q1.y + a1.z*q1.z + a1.w*q1.w
                  + a2.x*q2.x + a2.y*q2.y + a2.z*q2.z + a2.w*q2.w
                  + a3.x*q3.x + a3.y*q3.y + a3.z*q3.z + a3.w*q3.w;
        float rr  = a0.x*a0.x + a0.y*a0.y + a0.z*a0.z + a0.w*a0.w
                  + a1.x*a1.x + a1.y*a1.y + a1.z*a1.z + a1.w*a1.w
                  + a2.x*a2.x + a2.y*a2.y + a2.z*a2.z + a2.w*a2.w
                  + a3.x*a3.x + a3.y*a3.y + a3.z*a3.z + a3.w*a3.w;
        #pragma unroll
        for (int o = 16; o; o >>= 1) {
            dot += __shfl_xor_sync(0xFFFFFFFFu, dot, o);
            rr  += __shfl_xor_sync(0xFFFFFFFFu, rr, o);
        }
        if (lane == 0)
            skeys[local] = make_key(dot * rsqrtf(rr + 1e-12f), (unsigned)(rbeg + local));
        a0 = b0; a1 = b1; a2 = b2; a3 = b3;
        local = nlocal;
    }
    __syncthreads();

    // block top-11 over <=176 keys (1 per thread; threads >= SKN contribute 0)
    for (int r = 0; r < KTOP; r++) {
        unsigned long long v = (t < SKN) ? skeys[t] : 0ULL;
        unsigned long long w = block_max_u64(v, sh);
        if (t == 0) g_cand[blockIdx.x * KTOP + r] = w;
        if (t < SKN && skeys[t] == w) skeys[t] = 0ULL;   // keys unique (index embedded)
        __syncthreads();
    }
}

// ---------- Kernel 2: parallel merge, 64 blocks x 256 keys -> 704 survivors ----------
__global__ void __launch_bounds__(256) merge_kernel(int ncand) {
    __shared__ unsigned long long sh[33];
    int t = threadIdx.x;
    int i = blockIdx.x * 256 + t;
    unsigned long long key = (i < ncand) ? g_cand[i] : 0ULL;

    for (int r = 0; r < KTOP; r++) {
        unsigned long long w = block_max_u64(key, sh);
        if (t == 0) g_cand2[blockIdx.x * KTOP + r] = w;
        if (key == w) key = 0ULL;                // keys unique: one owner
    }
}

// ---------- Kernel 3: final merge of 704 keys, vote, output ----------
__global__ void __launch_bounds__(256) finalize(
        const float* __restrict__ emb, const int* __restrict__ labels,
        float* __restrict__ out, int out_size) {
    __shared__ unsigned long long sh[33];
    __shared__ unsigned long long top[KTOP];
    __shared__ float sred[8];

    int t = threadIdx.x;
    unsigned long long k0 = (t < NC2) ? g_cand2[t] : 0ULL;
    unsigned long long k1 = (t + 256 < NC2) ? g_cand2[t + 256] : 0ULL;
    unsigned long long k2 = (t + 512 < NC2) ? g_cand2[t + 512] : 0ULL;

    for (int r = 0; r < KTOP; r++) {
        unsigned long long m = k0 > k1 ? k0 : k1;
        if (k2 > m) m = k2;
        unsigned long long w = block_max_u64(m, sh);
        if (t == 0) top[r] = w;
        if (k0 == w) k0 = 0ULL;
        if (k1 == w) k1 = 0ULL;
        if (k2 == w) k2 = 0ULL;
    }

    // ||q||^2
    float q0 = emb[t], q1 = emb[t + 256];
    float s = q0 * q0 + q1 * q1;
    #pragma unroll
    for (int o = 16; o; o >>= 1) s += __shfl_xor_sync(0xFFFFFFFFu, s, o);
    if ((t & 31) == 0) sred[t >> 5] = s;
    __syncthreads();

    if (t == 0) {
        float qq = 0.f;
        #pragma unroll
        for (int w = 0; w < 8; w++) qq += sred[w];
        float inv_q = 1.0f / sqrtf(qq + 1e-12f);

        float vals[KTOP]; int idxs[KTOP];
        #pragma unroll
        for (int i = 0; i < KTOP; i++) {
            vals[i] = key_val(top[i]) * inv_q;
            idxs[i] = (int)key_idx(top[i]);
        }
        int preds[KNEI];
        #pragma unroll
        for (int j = 0; j < KNEI; j++) preds[j] = labels[idxs[1 + j]];

        int counts[NCLS];
        #pragma unroll
        for (int c = 0; c < NCLS; c++) counts[c] = 0;
        #pragma unroll
        for (int j = 0; j < KNEI; j++) {
            int p = preds[j];
            if (p >= 0 && p < NCLS) counts[p]++;
        }
        int best = 0;
        for (int c = 1; c < NCLS; c++)
            if (counts[c] > counts[best]) best = c;   // first-occurrence argmax
        int pos = 0;
        for (int j = KNEI - 1; j >= 0; j--)
            if (preds[j] == best) pos = j;            // first match
        float conf = vals[1 + pos];

        int m = out_size < KTOP ? out_size : KTOP;
        for (int i = 0; i < m; i++) out[i] = vals[i];
        if (out_size > KTOP)     out[KTOP]     = (float)best;
        if (out_size > KTOP + 1) out[KTOP + 1] = conf;
        for (int i = KTOP + 2; i < out_size; i++) out[i] = 0.0f;
    }
}

extern "C" void kernel_launch(void* const* d_in, const int* in_sizes, int n_in,
                              void* d_out, int out_size) {
    const float* emb    = (const float*)d_in[0];
    const float* coll   = (const float*)d_in[1];
    const int*   labels = (const int*)d_in[2];   // jnp.int64 canonicalizes to int32 (no x64)
    int n = in_sizes[1] / D;   // 250000

    score_topk_kernel<<<GRID1, 256>>>(coll, emb, n);
    merge_kernel<<<MBLK, 256>>>(GRID1 * KTOP);
    finalize<<<1, 256>>>(emb, labels, (float*)d_out, out_size);
}

// round 10
// speedup vs baseline: 1.0265x; 1.0265x over previous
#include <cuda_runtime.h>
#include <cuda_bf16.h>
#include <math.h>

#define D     512
#define KTOP  11          // 1 + K
#define KNEI  9           // reference uses idx[1:K] = 9 neighbors
#define NCLS  100
#define NMAX  250000
#define TB2   64          // topk blocks
#define KPT   16          // keys per thread in topk (64*256*16 = 262144 >= N)
#define NC2   (TB2 * KTOP)   // 704

// Scratch (allocation-free rule: __device__ globals)
__device__ float              g_scores[NMAX];
__device__ unsigned long long g_cand2[NC2];

// ---- monotonic float key: bigger key == bigger value; tie -> smaller index wins ----
__device__ __forceinline__ unsigned long long make_key(float v, unsigned int idx) {
    unsigned int b = __float_as_uint(v);
    b = (b & 0x80000000u) ? ~b : (b | 0x80000000u);
    return ((unsigned long long)b << 32) | (unsigned int)(~idx);
}
__device__ __forceinline__ float key_val(unsigned long long k) {
    unsigned int o = (unsigned int)(k >> 32);
    unsigned int b = (o & 0x80000000u) ? (o ^ 0x80000000u) : ~o;
    return __uint_as_float(b);
}
__device__ __forceinline__ unsigned int key_idx(unsigned long long k) {
    return ~(unsigned int)(k & 0xFFFFFFFFu);
}

__device__ __forceinline__ unsigned long long block_max_u64(unsigned long long v,
                                                            unsigned long long* sh) {
    #pragma unroll
    for (int o = 16; o; o >>= 1) {
        unsigned long long u = __shfl_xor_sync(0xFFFFFFFFu, v, o);
        if (u > v) v = u;
    }
    int warp = threadIdx.x >> 5, lane = threadIdx.x & 31;
    if (lane == 0) sh[warp] = v;
    __syncthreads();
    if (warp == 0) {
        int nw = (blockDim.x + 31) >> 5;
        v = (lane < nw) ? sh[lane] : 0ULL;
        #pragma unroll
        for (int o = 4; o; o >>= 1) {
            unsigned long long u = __shfl_xor_sync(0xFFFFFFFFu, v, o);
            if (u > v) v = u;
        }
        if (lane == 0) sh[0] = v;
    }
    __syncthreads();
    unsigned long long r = sh[0];
    __syncthreads();
    return r;
}

// ---------- Kernel 1 (R2-exact): warp-per-row streaming, short-lived blocks ----------
__global__ void score_kernel(const float* __restrict__ coll,
                             const float* __restrict__ emb, int n) {
    __shared__ float4 sq[D / 4];
    int t = threadIdx.x;
    if (t < D / 4) sq[t] = reinterpret_cast<const float4*>(emb)[t];
    __syncthreads();

    int warp = t >> 5, lane = t & 31;
    int row = blockIdx.x * 8 + warp;
    if (row >= n) return;

    const float4* rp = reinterpret_cast<const float4*>(coll + (size_t)row * D);
    float dot = 0.f, rr = 0.f;
    #pragma unroll
    for (int j = 0; j < 4; j++) {
        float4 v = rp[lane + 32 * j];
        float4 q = sq[lane + 32 * j];
        dot += v.x * q.x + v.y * q.y + v.z * q.z + v.w * q.w;
        rr  += v.x * v.x + v.y * v.y + v.z * v.z + v.w * v.w;
    }
    #pragma unroll
    for (int o = 16; o; o >>= 1) {
        dot += __shfl_xor_sync(0xFFFFFFFFu, dot, o);
        rr  += __shfl_xor_sync(0xFFFFFFFFu, rr, o);
    }
    if (lane == 0)
        g_scores[row] = dot / sqrtf(rr + 1e-12f);   // q-norm scaling deferred (order-invariant)
}

// ---------- Kernel 2: 64-block top-11, 16 register keys/thread ----------
__global__ void __launch_bounds__(256) topk_partial(int n) {
    __shared__ unsigned long long sh[33];
    int t = threadIdx.x;
    unsigned long long keys[KPT];
    int base = blockIdx.x * 256 + t;
    #pragma unroll
    for (int j = 0; j < KPT; j++) {
        int i = base + j * (TB2 * 256);
        keys[j] = (i < n) ? make_key(g_scores[i], (unsigned)i) : 0ULL;
    }
    for (int r = 0; r < KTOP; r++) {
        unsigned long long m = keys[0];
        #pragma unroll
        for (int j = 1; j < KPT; j++) if (keys[j] > m) m = keys[j];
        unsigned long long w = block_max_u64(m, sh);
        if (t == 0) g_cand2[blockIdx.x * KTOP + r] = w;
        #pragma unroll
        for (int j = 0; j < KPT; j++) if (keys[j] == w) keys[j] = 0ULL;  // unique keys
    }
}

// ---------- Kernel 3: final merge of 704 keys, vote, output ----------
__global__ void __launch_bounds__(256) finalize(
        const float* __restrict__ emb, const int* __restrict__ labels,
        float* __restrict__ out, int out_size) {
    __shared__ unsigned long long sh[33];
    __shared__ unsigned long long top[KTOP];
    __shared__ float sred[8];

    int t = threadIdx.x;
    unsigned long long k0 = (t < NC2) ? g_cand2[t] : 0ULL;
    unsigned long long k1 = (t + 256 < NC2) ? g_cand2[t + 256] : 0ULL;
    unsigned long long k2 = (t + 512 < NC2) ? g_cand2[t + 512] : 0ULL;

    for (int r = 0; r < KTOP; r++) {
        unsigned long long m = k0 > k1 ? k0 : k1;
        if (k2 > m) m = k2;
        unsigned long long w = block_max_u64(m, sh);
        if (t == 0) top[r] = w;
        if (k0 == w) k0 = 0ULL;
        if (k1 == w) k1 = 0ULL;
        if (k2 == w) k2 = 0ULL;
    }

    // ||q||^2
    float q0 = emb[t], q1 = emb[t + 256];
    float s = q0 * q0 + q1 * q1;
    #pragma unroll
    for (int o = 16; o; o >>= 1) s += __shfl_xor_sync(0xFFFFFFFFu, s, o);
    if ((t & 31) == 0) sred[t >> 5] = s;
    __syncthreads();

    if (t == 0) {
        float qq = 0.f;
        #pragma unroll
        for (int w = 0; w < 8; w++) qq += sred[w];
        float inv_q = 1.0f / sqrtf(qq + 1e-12f);

        float vals[KTOP]; int idxs[KTOP];
        #pragma unroll
        for (int i = 0; i < KTOP; i++) {
            vals[i] = key_val(top[i]) * inv_q;
            idxs[i] = (int)key_idx(top[i]);
        }
        int preds[KNEI];
        #pragma unroll
        for (int j = 0; j < KNEI; j++) preds[j] = labels[idxs[1 + j]];

        int counts[NCLS];
        #pragma unroll
        for (int c = 0; c < NCLS; c++) counts[c] = 0;
        #pragma unroll
        for (int j = 0; j < KNEI; j++) {
            int p = preds[j];
            if (p >= 0 && p < NCLS) counts[p]++;
        }
        int best = 0;
        for (int c = 1; c < NCLS; c++)
            if (counts[c] > counts[best]) best = c;   // first-occurrence argmax
        int pos = 0;
        for (int j = KNEI - 1; j >= 0; j--)
            if (preds[j] == best) pos = j;            // first match
        float conf = vals[1 + pos];

        int m = out_size < KTOP ? out_size : KTOP;
        for (int i = 0; i < m; i++) out[i] = vals[i];
        if (out_size > KTOP)     out[KTOP]     = (float)best;
        if (out_size > KTOP + 1) out[KTOP + 1] = conf;
        for (int i = KTOP + 2; i < out_size; i++) out[i] = 0.0f;
    }
}

extern "C" void kernel_launch(void* const* d_in, const int* in_sizes, int n_in,
                              void* d_out, int out_size) {
    const float* emb    = (const float*)d_in[0];
    const float* coll   = (const float*)d_in[1];
    const int*   labels = (const int*)d_in[2];   // jnp.int64 canonicalizes to int32 (no x64)
    int n = in_sizes[1] / D;   // 250000

    score_kernel<<<(n + 7) / 8, 256>>>(coll, emb, n);
    topk_partial<<<TB2, 256>>>(n);
    finalize<<<1, 256>>>(emb, labels, (float*)d_out, out_size);
}